// round 4
// baseline (speedup 1.0000x reference)
#include <cuda_runtime.h>
#include <cuda_bf16.h>

// ---------------------------------------------------------------------------
// EncdecProbLossSigmoid:
//   loss = mean_{gt} softplus(-x_gt)                     (loss_gt)
//        + (Sum_all softplus(x) - Sum_gt softplus(x_gt)) / (B*S*(V-1))
// where softplus(x) = max(x,0) + log1p(exp(-|x|)).
//
// Strategy: single streaming pass over 512MB of logits (HBM-bound),
// 2 MUFU ops/element (ex2.approx + lg2.approx), fp32 per-thread partials,
// block reduce, double atomics into __device__ scratch, tiny gt + finalize
// kernels. All graph-capturable, no allocations.
//
// R1 fix: tokens are int32 (JAX x64-disabled downcasts int64 -> int32);
// reading them as int64 caused OOB reads + garbage logits indices -> IMA.
// R2/R3 failures were container acquisition (broker infra) — the fixed
// kernel has not yet executed. Resubmitting unchanged.
// ---------------------------------------------------------------------------

__device__ double g_A;   // Sum over all elements of softplus(x)
__device__ double g_G1;  // Sum over gt positions of softplus(-x_gt)
__device__ double g_G2;  // Sum over gt positions of softplus(+x_gt)

__global__ void init_kernel() {
    g_A = 0.0; g_G1 = 0.0; g_G2 = 0.0;
}

__device__ __forceinline__ float ex2f(float x) {
    float y;
    asm("ex2.approx.ftz.f32 %0, %1;" : "=f"(y) : "f"(x));
    return y;
}
__device__ __forceinline__ float lg2f(float x) {
    float y;
    asm("lg2.approx.ftz.f32 %0, %1;" : "=f"(y) : "f"(x));
    return y;
}

// Block-wide float reduce (256 threads), returns total on thread 0.
__device__ __forceinline__ float block_reduce_256(float v) {
    #pragma unroll
    for (int m = 16; m > 0; m >>= 1)
        v += __shfl_xor_sync(0xFFFFFFFFu, v, m);
    __shared__ float s[8];
    int lane = threadIdx.x & 31;
    int wid  = threadIdx.x >> 5;
    if (lane == 0) s[wid] = v;
    __syncthreads();
    if (wid == 0) {
        v = (lane < 8) ? s[lane] : 0.0f;
        #pragma unroll
        for (int m = 4; m > 0; m >>= 1)
            v += __shfl_xor_sync(0xFFFFFFFFu, v, m);
    }
    return v;
}

// Main streaming kernel: A += sum softplus(x) over all logits.
// softplus(x) = max(x,0) + ln2 * lg2(1 + 2^(-|x| * log2(e)))
__global__ void __launch_bounds__(256) sum_all_kernel(
    const float4* __restrict__ p4, int n4,
    const float* __restrict__ p, int n_total)
{
    const float NL2E = -1.4426950408889634f;  // -log2(e)
    float accM0 = 0.0f, accM1 = 0.0f;
    float accL0 = 0.0f, accL1 = 0.0f;

    int stride = gridDim.x * blockDim.x;
    for (int i = blockIdx.x * blockDim.x + threadIdx.x; i < n4; i += stride) {
        float4 v = __ldcs(&p4[i]);

        accM0 += fmaxf(v.x, 0.0f);
        accL0 += lg2f(1.0f + ex2f(NL2E * fabsf(v.x)));
        accM1 += fmaxf(v.y, 0.0f);
        accL1 += lg2f(1.0f + ex2f(NL2E * fabsf(v.y)));
        accM0 += fmaxf(v.z, 0.0f);
        accL0 += lg2f(1.0f + ex2f(NL2E * fabsf(v.z)));
        accM1 += fmaxf(v.w, 0.0f);
        accL1 += lg2f(1.0f + ex2f(NL2E * fabsf(v.w)));
    }

    // Scalar tail (none for this shape, kept for generality).
    for (int i = n4 * 4 + blockIdx.x * blockDim.x + threadIdx.x;
         i < n_total; i += stride) {
        float x = __ldcs(&p[i]);
        accM0 += fmaxf(x, 0.0f);
        accL0 += lg2f(1.0f + ex2f(NL2E * fabsf(x)));
    }

    float part = (accM0 + accM1)
               + 0.69314718055994531f * (accL0 + accL1);

    float total = block_reduce_256(part);
    if (threadIdx.x == 0)
        atomicAdd(&g_A, (double)total);
}

// GT kernel: 4096 positions; precise math (cost negligible).
// Tokens are int32 (see header note). Index clamped defensively.
__global__ void __launch_bounds__(256) gt_kernel(
    const float* __restrict__ logits,
    const int* __restrict__ tokens,
    int BS, int V)
{
    int i = blockIdx.x * blockDim.x + threadIdx.x;
    float sp_pos = 0.0f, sp_neg = 0.0f;
    if (i < BS) {
        int t = tokens[i];
        if (t < 0) t = 0;
        if (t >= V) t = V - 1;
        float x = logits[(size_t)i * (size_t)V + (size_t)t];
        float l = log1pf(expf(-fabsf(x)));
        sp_pos = fmaxf(x, 0.0f) + l;   // softplus(+x)
        sp_neg = fmaxf(-x, 0.0f) + l;  // softplus(-x)
    }
    float tp = block_reduce_256(sp_pos);
    __syncthreads();   // block_reduce_256 reuses shared mem
    float tn = block_reduce_256(sp_neg);
    if (threadIdx.x == 0) {
        atomicAdd(&g_G2, (double)tp);
        atomicAdd(&g_G1, (double)tn);
    }
}

__global__ void finalize_kernel(float* __restrict__ out, int BS, long long denom_all) {
    double loss = g_G1 / (double)BS + (g_A - g_G2) / (double)denom_all;
    out[0] = (float)loss;
}

extern "C" void kernel_launch(void* const* d_in, const int* in_sizes, int n_in,
                              void* d_out, int out_size)
{
    const float* logits = (const float*)d_in[0];
    const int*   tokens = (const int*)d_in[1];
    float*       out    = (float*)d_out;

    int n_logits = in_sizes[0];           // B*S*V = 131072000
    int BS       = in_sizes[1];           // B*S   = 4096
    int V        = n_logits / BS;         // 32000
    int n4       = n_logits / 4;

    long long denom_all = (long long)BS * (long long)(V - 1);

    init_kernel<<<1, 1>>>();

    int blocks = 148 * 8;                 // near-full-occupancy grid
    int max_blocks = (n4 + 255) / 256;
    if (blocks > max_blocks) blocks = max_blocks;
    if (blocks < 1) blocks = 1;
    sum_all_kernel<<<blocks, 256>>>((const float4*)logits, n4, logits, n_logits);

    gt_kernel<<<(BS + 255) / 256, 256>>>(logits, tokens, BS, V);

    finalize_kernel<<<1, 1>>>(out, BS, denom_all);
}

// round 5
// speedup vs baseline: 1.1135x; 1.1135x over previous
#include <cuda_runtime.h>
#include <cuda_bf16.h>

// ---------------------------------------------------------------------------
// EncdecProbLossSigmoid — single fused kernel.
//   loss = G1/(B*S) + (A - G2)/(B*S*(V-1))
//   A  = sum_all softplus(x),  G1 = sum_gt softplus(-x),  G2 = sum_gt softplus(x)
//   softplus(x) = max(x,0) + ln2 * lg2(1 + 2^(-|x|*log2e))   [2 MUFU/elem]
//
// R4: 4-kernel version passed at 94.2us; ~12us of that was serialized tiny
// kernels (finalize alone 4.99us). R5 fuses init/gt/finalize into the
// streaming kernel via per-block partials + last-block-done reduction
// (threadfence + atomic counter, counter self-resets -> graph-replay safe).
// Stream split in halves: 2 independent LDG.128 per iteration for MLP.
// ---------------------------------------------------------------------------

#define NBLOCKS 1184   // 148 SMs * 8 CTAs (256 thr) = full occupancy

__device__ float4       g_partials[NBLOCKS];  // (A, G1, G2, unused) per block
__device__ unsigned int g_count;              // zero-init; self-resets each run

__device__ __forceinline__ float ex2f(float x) {
    float y; asm("ex2.approx.ftz.f32 %0, %1;" : "=f"(y) : "f"(x)); return y;
}
__device__ __forceinline__ float lg2f(float x) {
    float y; asm("lg2.approx.ftz.f32 %0, %1;" : "=f"(y) : "f"(x)); return y;
}

// Block-wide float reduce (256 threads); total valid on thread 0.
__device__ __forceinline__ float block_reduce_f(float v) {
    #pragma unroll
    for (int m = 16; m > 0; m >>= 1) v += __shfl_xor_sync(0xFFFFFFFFu, v, m);
    __shared__ float s[8];
    int lane = threadIdx.x & 31, wid = threadIdx.x >> 5;
    if (lane == 0) s[wid] = v;
    __syncthreads();
    if (wid == 0) {
        v = (lane < 8) ? s[lane] : 0.0f;
        #pragma unroll
        for (int m = 4; m > 0; m >>= 1) v += __shfl_xor_sync(0xFFFFFFFFu, v, m);
    }
    return v;
}

__device__ __forceinline__ void sp_acc(float x, float& accM, float& accL) {
    const float NL2E = -1.4426950408889634f;  // -log2(e)
    accM += fmaxf(x, 0.0f);
    accL += lg2f(1.0f + ex2f(NL2E * fabsf(x)));
}

__global__ void __launch_bounds__(256) fused_loss_kernel(
    const float* __restrict__ p, int n_total,
    const int* __restrict__ tokens, int BS, int V,
    double denom_all, float* __restrict__ out)
{
    const float4* p4 = (const float4*)p;
    const int n4    = n_total >> 2;
    const int half4 = n4 >> 1;

    const int tid0   = blockIdx.x * blockDim.x + threadIdx.x;
    const int stride = gridDim.x * blockDim.x;

    float accM0 = 0.f, accM1 = 0.f, accL0 = 0.f, accL1 = 0.f;

    // Main stream: two independent LDG.128 per iteration (MLP=2).
    for (int i = tid0; i < half4; i += stride) {
        float4 a = __ldcs(&p4[i]);
        float4 b = __ldcs(&p4[i + half4]);
        sp_acc(a.x, accM0, accL0); sp_acc(a.y, accM1, accL1);
        sp_acc(a.z, accM0, accL0); sp_acc(a.w, accM1, accL1);
        sp_acc(b.x, accM0, accL0); sp_acc(b.y, accM1, accL1);
        sp_acc(b.z, accM0, accL0); sp_acc(b.w, accM1, accL1);
    }
    // float4 leftover when n4 is odd.
    for (int i = 2 * half4 + tid0; i < n4; i += stride) {
        float4 v = __ldcs(&p4[i]);
        sp_acc(v.x, accM0, accL0); sp_acc(v.y, accM1, accL1);
        sp_acc(v.z, accM0, accL0); sp_acc(v.w, accM1, accL1);
    }
    // Scalar tail (n_total % 4).
    for (int i = (n4 << 2) + tid0; i < n_total; i += stride)
        sp_acc(__ldcs(&p[i]), accM0, accL0);

    float partA = (accM0 + accM1) + 0.69314718055994531f * (accL0 + accL1);

    // GT terms: first BS global threads (tokens are int32; clamp defensively).
    float g1 = 0.f, g2 = 0.f;
    if (tid0 < BS) {
        int t = tokens[tid0];
        if (t < 0) t = 0;
        if (t >= V) t = V - 1;
        float x = p[(size_t)tid0 * (size_t)V + (size_t)t];
        float l = log1pf(expf(-fabsf(x)));
        g2 = fmaxf(x, 0.0f) + l;    // softplus(+x)
        g1 = fmaxf(-x, 0.0f) + l;   // softplus(-x)
    }

    partA = block_reduce_f(partA);
    __syncthreads();
    // Only the first few blocks carry gt terms; others store zeros directly.
    if (blockIdx.x < (unsigned)((BS + blockDim.x - 1) / blockDim.x)) {
        g1 = block_reduce_f(g1);
        __syncthreads();
        g2 = block_reduce_f(g2);
    }

    __shared__ bool s_last;
    if (threadIdx.x == 0) {
        g_partials[blockIdx.x] = make_float4(partA, g1, g2, 0.0f);
        __threadfence();
        unsigned v = atomicAdd(&g_count, 1u);
        s_last = (v == gridDim.x - 1);
    }
    __syncthreads();

    // Last block: reduce all partials in double, finalize, reset counter.
    if (s_last) {
        double a = 0.0, b = 0.0, c = 0.0;
        for (int i = threadIdx.x; i < gridDim.x; i += blockDim.x) {
            float4 v = g_partials[i];
            a += (double)v.x; b += (double)v.y; c += (double)v.z;
        }
        #pragma unroll
        for (int m = 16; m > 0; m >>= 1) {
            a += __shfl_xor_sync(0xFFFFFFFFu, a, m);
            b += __shfl_xor_sync(0xFFFFFFFFu, b, m);
            c += __shfl_xor_sync(0xFFFFFFFFu, c, m);
        }
        __shared__ double sa[8], sb[8], sc[8];
        int lane = threadIdx.x & 31, wid = threadIdx.x >> 5;
        if (lane == 0) { sa[wid] = a; sb[wid] = b; sc[wid] = c; }
        __syncthreads();
        if (threadIdx.x == 0) {
            for (int i = 1; i < 8; i++) { a += sa[i]; b += sb[i]; c += sc[i]; }
            double loss = b / (double)BS + (a - c) / denom_all;
            out[0] = (float)loss;
            g_count = 0;              // self-reset for next graph replay
        }
    }
}

extern "C" void kernel_launch(void* const* d_in, const int* in_sizes, int n_in,
                              void* d_out, int out_size)
{
    const float* logits = (const float*)d_in[0];
    const int*   tokens = (const int*)d_in[1];
    float*       out    = (float*)d_out;

    int n_logits = in_sizes[0];           // B*S*V = 131072000
    int BS       = in_sizes[1];           // B*S   = 4096
    int V        = n_logits / BS;         // 32000

    double denom_all = (double)BS * (double)(V - 1);

    fused_loss_kernel<<<NBLOCKS, 256>>>(logits, n_logits, tokens, BS, V,
                                        denom_all, out);
}

// round 8
// speedup vs baseline: 1.1762x; 1.0563x over previous
#include <cuda_runtime.h>
#include <cuda_bf16.h>

// ---------------------------------------------------------------------------
// EncdecProbLossSigmoid — single fused kernel, log-of-products softplus.
//   loss = G1/(B*S) + (A - G2)/(B*S*(V-1))
//   A = sum softplus(x); softplus(x) = max(x,0) + ln2*log2(1 + 2^(-|x|log2e))
//
// R5 -> R6: MUFU was the near-binding pipe (2 MUFU/elem = ~70-82% of the
// memory window). Batch the lg2: sum log2(1+t_i) = log2(prod(1+t_i)) over 8
// elements -> 1.125 MUFU/elem. Product built with FFMA chains (idle fma pipe).
// R6, R7 runs both died in container acquisition (bare broker RuntimeError,
// same signature as R0/R2/R3 flakes) — kernel never executed. Attempt 3,
// unchanged, to preserve the R5 -> R6 A/B attribution.
// ---------------------------------------------------------------------------

#define NBLOCKS 1184   // 148 SMs * 8 CTAs (256 thr)

__device__ float4       g_partials[NBLOCKS];  // (A, G1, G2, -) per block
__device__ unsigned int g_count;              // zero-init; self-resets

__device__ __forceinline__ float ex2f(float x) {
    float y; asm("ex2.approx.ftz.f32 %0, %1;" : "=f"(y) : "f"(x)); return y;
}
__device__ __forceinline__ float lg2f(float x) {
    float y; asm("lg2.approx.ftz.f32 %0, %1;" : "=f"(y) : "f"(x)); return y;
}

#define NL2E (-1.4426950408889634f)  /* -log2(e) */

// Per-float4: accumulate max(x,0) terms, return product of (1+t_i), t=2^(-|x|l2e).
__device__ __forceinline__ float chain4(float4 v, float& accM0, float& accM1) {
    float t0 = ex2f(NL2E * fabsf(v.x));
    float t1 = ex2f(NL2E * fabsf(v.y));
    float t2 = ex2f(NL2E * fabsf(v.z));
    float t3 = ex2f(NL2E * fabsf(v.w));
    accM0 += fmaxf(v.x, 0.0f);
    accM1 += fmaxf(v.y, 0.0f);
    accM0 += fmaxf(v.z, 0.0f);
    accM1 += fmaxf(v.w, 0.0f);
    float f = 1.0f + t0;
    f = __fmaf_rn(t1, f, f);   // f *= (1+t1)
    f = __fmaf_rn(t2, f, f);
    f = __fmaf_rn(t3, f, f);
    return f;                  // in [1, 16]
}

// Block-wide float reduce (256 threads); total valid on thread 0.
__device__ __forceinline__ float block_reduce_f(float v) {
    #pragma unroll
    for (int m = 16; m > 0; m >>= 1) v += __shfl_xor_sync(0xFFFFFFFFu, v, m);
    __shared__ float s[8];
    int lane = threadIdx.x & 31, wid = threadIdx.x >> 5;
    if (lane == 0) s[wid] = v;
    __syncthreads();
    if (wid == 0) {
        v = (lane < 8) ? s[lane] : 0.0f;
        #pragma unroll
        for (int m = 4; m > 0; m >>= 1) v += __shfl_xor_sync(0xFFFFFFFFu, v, m);
    }
    return v;
}

__global__ void __launch_bounds__(256, 8) fused_loss_kernel(
    const float* __restrict__ p, int n_total,
    const int* __restrict__ tokens, int BS, int V,
    double denom_all, float* __restrict__ out)
{
    const float4* p4 = (const float4*)p;
    const int n4    = n_total >> 2;
    const int half4 = n4 >> 1;

    const int tid0   = blockIdx.x * blockDim.x + threadIdx.x;
    const int stride = gridDim.x * blockDim.x;

    float accM0 = 0.f, accM1 = 0.f, accL = 0.f;

    // Main stream: two independent LDG.128 per iteration; one lg2 per 8 elems.
    for (int i = tid0; i < half4; i += stride) {
        float4 a = __ldcs(&p4[i]);
        float4 b = __ldcs(&p4[i + half4]);
        float qa = chain4(a, accM0, accM1);
        float qb = chain4(b, accM0, accM1);
        accL += lg2f(qa * qb);
    }
    // float4 leftover when n4 is odd.
    for (int i = 2 * half4 + tid0; i < n4; i += stride) {
        float4 v = __ldcs(&p4[i]);
        accL += lg2f(chain4(v, accM0, accM1));
    }
    // Scalar tail (n_total % 4).
    for (int i = (n4 << 2) + tid0; i < n_total; i += stride) {
        float x = __ldcs(&p[i]);
        accM0 += fmaxf(x, 0.0f);
        accL += lg2f(1.0f + ex2f(NL2E * fabsf(x)));
    }

    float partA = (accM0 + accM1) + 0.69314718055994531f * accL;

    // GT terms: first BS global threads (tokens int32; clamp defensively).
    float g1 = 0.f, g2 = 0.f;
    if (tid0 < BS) {
        int t = tokens[tid0];
        if (t < 0) t = 0;
        if (t >= V) t = V - 1;
        float x = p[(size_t)tid0 * (size_t)V + (size_t)t];
        float l = log1pf(expf(-fabsf(x)));
        g2 = fmaxf(x, 0.0f) + l;    // softplus(+x)
        g1 = fmaxf(-x, 0.0f) + l;   // softplus(-x)
    }

    partA = block_reduce_f(partA);
    __syncthreads();
    if (blockIdx.x < (unsigned)((BS + blockDim.x - 1) / blockDim.x)) {
        g1 = block_reduce_f(g1);
        __syncthreads();
        g2 = block_reduce_f(g2);
    }

    __shared__ bool s_last;
    if (threadIdx.x == 0) {
        g_partials[blockIdx.x] = make_float4(partA, g1, g2, 0.0f);
        __threadfence();
        unsigned v = atomicAdd(&g_count, 1u);
        s_last = (v == gridDim.x - 1);
    }
    __syncthreads();

    // Last block: reduce partials in double, finalize, reset counter.
    if (s_last) {
        double a = 0.0, b = 0.0, c = 0.0;
        for (int i = threadIdx.x; i < gridDim.x; i += blockDim.x) {
            float4 v = g_partials[i];
            a += (double)v.x; b += (double)v.y; c += (double)v.z;
        }
        #pragma unroll
        for (int m = 16; m > 0; m >>= 1) {
            a += __shfl_xor_sync(0xFFFFFFFFu, a, m);
            b += __shfl_xor_sync(0xFFFFFFFFu, b, m);
            c += __shfl_xor_sync(0xFFFFFFFFu, c, m);
        }
        __shared__ double sa[8], sb[8], sc[8];
        int lane = threadIdx.x & 31, wid = threadIdx.x >> 5;
        if (lane == 0) { sa[wid] = a; sb[wid] = b; sc[wid] = c; }
        __syncthreads();
        if (threadIdx.x == 0) {
            for (int i = 1; i < 8; i++) { a += sa[i]; b += sb[i]; c += sc[i]; }
            double loss = b / (double)BS + (a - c) / denom_all;
            out[0] = (float)loss;
            g_count = 0;              // self-reset for next graph replay
        }
    }
}

extern "C" void kernel_launch(void* const* d_in, const int* in_sizes, int n_in,
                              void* d_out, int out_size)
{
    const float* logits = (const float*)d_in[0];
    const int*   tokens = (const int*)d_in[1];
    float*       out    = (float*)d_out;

    int n_logits = in_sizes[0];           // B*S*V
    int BS       = in_sizes[1];           // B*S
    int V        = n_logits / BS;

    double denom_all = (double)BS * (double)(V - 1);

    fused_loss_kernel<<<NBLOCKS, 256>>>(logits, n_logits, tokens, BS, V,
                                        denom_all, out);
}